// round 5
// baseline (speedup 1.0000x reference)
#include <cuda_runtime.h>

// LocalInfoNCELoss, row-split version:
// grid = 16 batches x 9 row-groups = 144 blocks (one wave).
// Each block gathers the FULL p(26,576) for its batch (L2-shared across the
// 9 sibling blocks), computes diag self-dots + its <=3 Gram rows, then its
// row losses locally. ONE global sync stage: atomicAdd(loss) + counter.

#define BSZ    16
#define Hh     192
#define Ww     192
#define Cc     64
#define KKp    9
#define Rr     13
#define TWO_R  26
#define Dd     576
#define TAU_INV 2.0f
#define NGRP   9            // row groups per batch
#define GRID   (BSZ * NGRP)

// dynamic smem: p[26*576] | diag[26] | rs[3*26] | rn[32] | rowloss[4] | off[234]
#define P_F     (TWO_R * Dd)
#define DIAG_F  P_F
#define RS_F    (DIAG_F + TWO_R)
#define RN_F    (RS_F + 3 * TWO_R)
#define RL_F    (RN_F + 32)
#define OFF_I   (RL_F + 4)
#define N_OFF   (TWO_R * KKp)
#define SMEM_BYTES ((OFF_I + N_OFF) * 4)

__device__ float    g_loss;
__device__ unsigned g_done;

__global__ __launch_bounds__(256, 1)
void infonce_rows(const float* __restrict__ f1, const float* __restrict__ f2,
                  const int* __restrict__ bi, const int* __restrict__ hi,
                  const int* __restrict__ wi, float* __restrict__ out)
{
    extern __shared__ float sm[];
    float* p       = sm;
    float* diag    = sm + DIAG_F;
    float* rs      = sm + RS_F;
    float* rn      = sm + RN_F;
    float* rowloss = sm + RL_F;
    int*   off     = (int*)(sm + OFF_I);

    const int blk   = blockIdx.x;
    const int b     = blk / NGRP;
    const int g     = blk - b * NGRP;
    const int r0    = g * 3;                       // first owned row
    const int nrows = (g == 8) ? 2 : 3;            // 8*3+2 = 26
    const int tid   = threadIdx.x;
    const int warp  = tid >> 5;
    const int lane  = tid & 31;

    // ---- Phase 0: all 234 base offsets (26 rows x 9 pixels) ----
    if (tid < N_OFF) {
        int i  = tid / KKp;
        int kk = tid - i * KKp;
        int r  = (i < Rr) ? i : (i - Rr);
        int l  = (r * BSZ + b) * KKp + kk;
        off[tid] = ((bi[l] * Hh + hi[l]) * Ww + wi[l]) * Cc;
    }
    __syncthreads();

    // ---- Phase 1: gather full p(26 x 576) as float4 (3744 loads) ----
    #pragma unroll 4
    for (int idx = tid; idx < TWO_R * 144; idx += 256) {
        int i   = idx / 144;
        int rem = idx - i * 144;
        int kk  = rem >> 4;
        int v   = rem & 15;
        const float* f = (i < Rr) ? f1 : f2;
        ((float4*)(p + i * Dd))[rem] = *(const float4*)(f + off[i * KKp + kk] + v * 4);
    }
    __syncthreads();

    // ---- Phase 2: dots. t<26: diag(t,t); else row dots (r0+q/26, q%26) ----
    const int ndots = TWO_R + nrows * TWO_R;
    for (int t = warp; t < ndots; t += 8) {
        int i, j, q = -1;
        if (t < TWO_R) { i = t; j = t; }
        else {
            q = t - TWO_R;
            i = r0 + q / TWO_R;
            j = q - (q / TWO_R) * TWO_R;
        }
        const float* A = p + i * Dd;
        const float* B = p + j * Dd;
        float acc = 0.f;
        #pragma unroll
        for (int k = 0; k < Dd / 32; k++) {
            int d = lane + k * 32;
            acc = fmaf(A[d], B[d], acc);
        }
        #pragma unroll
        for (int o = 16; o > 0; o >>= 1)
            acc += __shfl_down_sync(0xffffffffu, acc, o);
        if (lane == 0) {
            if (q < 0) diag[i] = acc;
            else       rs[q]   = acc;
        }
    }
    __syncthreads();

    // ---- Phase 3: reciprocal norms ----
    if (tid < TWO_R)
        rn[tid] = 1.f / fmaxf(sqrtf(diag[tid]), 1e-8f);
    __syncthreads();

    // ---- Phase 4: row losses (warp w -> row r0+w), lane-parallel over j ----
    if (warp < nrows) {
        int i = r0 + warp;
        bool valid = (lane < TWO_R) && (lane != i);
        float v = valid ? rs[warp * TWO_R + lane] * rn[i] * rn[lane] * TAU_INV
                        : -1e30f;
        float m = v;
        #pragma unroll
        for (int o = 16; o > 0; o >>= 1)
            m = fmaxf(m, __shfl_xor_sync(0xffffffffu, m, o));
        float e = valid ? __expf(v - m) : 0.f;
        #pragma unroll
        for (int o = 16; o > 0; o >>= 1)
            e += __shfl_xor_sync(0xffffffffu, e, o);
        int partner = (i + Rr) % TWO_R;
        float pv = __shfl_sync(0xffffffffu, v, partner);
        if (lane == 0)
            rowloss[warp] = __logf(e) + m - pv;
    }
    __syncthreads();

    // ---- Phase 5: ONE global stage: add block loss, last block finalizes ----
    if (tid == 0) {
        float total = rowloss[0] + rowloss[1] + ((nrows == 3) ? rowloss[2] : 0.f);
        atomicAdd(&g_loss, total);
        __threadfence();
        if (atomicAdd(&g_done, 1u) == GRID - 1) {
            float tl = atomicAdd(&g_loss, 0.f);    // read full sum via L2
            out[0] = tl / (float)(BSZ * TWO_R);
            g_loss = 0.f;
            g_done = 0;
        }
    }
}

extern "C" void kernel_launch(void* const* d_in, const int* in_sizes, int n_in,
                              void* d_out, int out_size)
{
    const float* f1 = (const float*)d_in[0];
    const float* f2 = (const float*)d_in[1];
    const int*   bi = (const int*)d_in[2];
    const int*   hi = (const int*)d_in[3];
    const int*   wi = (const int*)d_in[4];
    float* out = (float*)d_out;

    cudaFuncSetAttribute(infonce_rows,
                         cudaFuncAttributeMaxDynamicSharedMemorySize, SMEM_BYTES);

    infonce_rows<<<GRID, 256, SMEM_BYTES>>>(f1, f2, bi, hi, wi, out);
}

// round 6
// speedup vs baseline: 1.0194x; 1.0194x over previous
#include <cuda_runtime.h>
#include <cooperative_groups.h>
namespace cg = cooperative_groups;

// LocalInfoNCELoss, cluster version:
// grid = 16 batches x 8 D-slices (72 each), cluster = the 8 slice CTAs.
// Each CTA: gather 26x72 -> partial Gram -> remote-store into rank0 smem.
// ONE cluster.sync. Rank 0: sum partials, norms, softmax, global loss stage.

#define BSZ    16
#define Hh     192
#define Ww     192
#define Cc     64
#define KKp    9
#define Rr     13
#define TWO_R  26
#define TAU_INV 2.0f
#define CLU    8
#define SLICE  72           // D per slice (8*72 = 576)
#define SPAD   96           // padded row length (zeros beyond 72)
#define F4ROW  18           // 72/4 float4 per row
#define N_TILES 7
#define N_TILE_PAIRS 28
#define SIMN   (TWO_R * TWO_R)
#define N_OFF  (TWO_R * KKp)
#define GRID   (BSZ * CLU)

__device__ float    g_loss;
__device__ unsigned g_done;

__global__ __launch_bounds__(256, 1) __cluster_dims__(CLU, 1, 1)
void infonce_cluster(const float* __restrict__ f1, const float* __restrict__ f2,
                     const int* __restrict__ bi, const int* __restrict__ hi,
                     const int* __restrict__ wi, float* __restrict__ out)
{
    __shared__ float p[28][SPAD];        // 26 rows + 2 zero rows, zero-padded cols
    __shared__ float part[CLU][SIMN];    // partial Grams (only rank 0's is used)
    __shared__ int   off[N_OFF];
    __shared__ float rn[32];
    __shared__ float rowloss[8];

    cg::cluster_group cluster = cg::this_cluster();
    const unsigned rank = cluster.block_rank();      // slice 0..7
    const int b    = blockIdx.x / CLU;               // batch
    const int tid  = threadIdx.x;
    const int warp = tid >> 5;
    const int lane = tid & 31;

    // ---- Phase 0: all 234 pixel base-offsets + zero p ----
    if (tid < N_OFF) {
        int i  = tid / KKp;
        int kk = tid - i * KKp;
        int r  = (i < Rr) ? i : (i - Rr);
        int l  = (r * BSZ + b) * KKp + kk;
        off[tid] = ((bi[l] * Hh + hi[l]) * Ww + wi[l]) * Cc;
    }
    for (int z = tid; z < 28 * SPAD / 4; z += 256)
        ((float4*)&p[0][0])[z] = make_float4(0.f, 0.f, 0.f, 0.f);
    __syncthreads();

    // ---- Phase 1: gather this slice: 26 rows x 18 float4 ----
    for (int idx = tid; idx < TWO_R * F4ROW; idx += 256) {
        int i  = idx / F4ROW;
        int t  = idx - i * F4ROW;
        int d0 = 4 * (F4ROW * (int)rank + t);   // element index in [0,576)
        int kk = d0 >> 6;                        // pixel
        int c  = d0 & 63;                        // channel
        const float* f = (i < Rr) ? f1 : f2;
        float4 v = *(const float4*)(f + off[i * KKp + kk] + c);
        ((float4*)p[i])[t] = v;
    }
    __syncthreads();

    // ---- Phase 2: partial Gram over 96 padded dims, write to rank0 DSMEM ----
    float* dst = (float*)cluster.map_shared_rank(&part[rank][0], 0);

    for (int t = warp; t < N_TILE_PAIRS; t += 8) {
        int ti = 0, tt = t;
        while (tt >= N_TILES - ti) { tt -= N_TILES - ti; ti++; }
        int tj = ti + tt;

        float acc[4][4];
        #pragma unroll
        for (int a = 0; a < 4; a++)
            #pragma unroll
            for (int c = 0; c < 4; c++) acc[a][c] = 0.f;

        #pragma unroll
        for (int k = 0; k < SPAD / 32; k++) {    // 3 iters, pad region is zeros
            int d = lane + k * 32;
            float av[4], bv[4];
            #pragma unroll
            for (int a = 0; a < 4; a++) av[a] = p[ti * 4 + a][d];
            #pragma unroll
            for (int c = 0; c < 4; c++) bv[c] = p[tj * 4 + c][d];
            #pragma unroll
            for (int a = 0; a < 4; a++)
                #pragma unroll
                for (int c = 0; c < 4; c++)
                    acc[a][c] = fmaf(av[a], bv[c], acc[a][c]);
        }
        #pragma unroll
        for (int a = 0; a < 4; a++) {
            #pragma unroll
            for (int c = 0; c < 4; c++) {
                float v = acc[a][c];
                #pragma unroll
                for (int o = 16; o > 0; o >>= 1)
                    v += __shfl_down_sync(0xffffffffu, v, o);
                if (lane == 0) {
                    int i = ti * 4 + a, j = tj * 4 + c;
                    if (i < TWO_R && j < TWO_R) {
                        dst[i * TWO_R + j] = v;
                        if (i != j) dst[j * TWO_R + i] = v;
                    }
                }
            }
        }
    }

    // ---- ONE cluster barrier: all partials delivered to rank 0 ----
    cluster.sync();
    if (rank != 0) return;

    // ---- Rank 0: sum 8 partials into part[0] ----
    for (int e = tid; e < SIMN; e += 256) {
        float s = part[0][e];
        #pragma unroll
        for (int r = 1; r < CLU; r++) s += part[r][e];
        part[0][e] = s;
    }
    __syncthreads();

    // ---- Norms ----
    if (tid < TWO_R)
        rn[tid] = 1.f / fmaxf(sqrtf(part[0][tid * TWO_R + tid]), 1e-8f);
    __syncthreads();

    // ---- Row losses: warp per row, lane-parallel over j ----
    float wl = 0.f;
    for (int i = warp; i < TWO_R; i += 8) {
        bool valid = (lane < TWO_R) && (lane != i);
        float v = valid ? part[0][i * TWO_R + lane] * rn[i] * rn[lane] * TAU_INV
                        : -1e30f;
        float m = v;
        #pragma unroll
        for (int o = 16; o > 0; o >>= 1)
            m = fmaxf(m, __shfl_xor_sync(0xffffffffu, m, o));
        float e = valid ? __expf(v - m) : 0.f;
        #pragma unroll
        for (int o = 16; o > 0; o >>= 1)
            e += __shfl_xor_sync(0xffffffffu, e, o);
        int partner = (i + Rr) % TWO_R;
        float pv = __shfl_sync(0xffffffffu, v, partner);
        if (lane == 0) wl += __logf(e) + m - pv;
    }
    if (lane == 0) rowloss[warp] = wl;
    __syncthreads();

    // ---- Final global stage: 16 rank-0 blocks ----
    if (tid == 0) {
        float total = 0.f;
        #pragma unroll
        for (int k = 0; k < 8; k++) total += rowloss[k];
        atomicAdd(&g_loss, total);
        __threadfence();
        if (atomicAdd(&g_done, 1u) == BSZ - 1) {
            float tl = atomicAdd(&g_loss, 0.f);
            out[0] = tl / (float)(BSZ * TWO_R);
            g_loss = 0.f;
            g_done = 0;
        }
    }
}

extern "C" void kernel_launch(void* const* d_in, const int* in_sizes, int n_in,
                              void* d_out, int out_size)
{
    const float* f1 = (const float*)d_in[0];
    const float* f2 = (const float*)d_in[1];
    const int*   bi = (const int*)d_in[2];
    const int*   hi = (const int*)d_in[3];
    const int*   wi = (const int*)d_in[4];
    float* out = (float*)d_out;

    infonce_cluster<<<GRID, 256>>>(f1, f2, bi, hi, wi, out);
}

// round 8
// speedup vs baseline: 1.1771x; 1.1546x over previous
#include <cuda_runtime.h>

// LocalInfoNCELoss, split-D (R3 skeleton) with latency trims:
// grid = 16 batches x 9 pixel-slices = 144 blocks (one wave).
// Each block: fused offset+gather (26x64 slice) -> partial Gram -> red to
// global. 9th block per batch: vectorized reload, softmax, row losses.
// 16th finishing batch: sum 16 block losses, write out, reset state.

#define BSZ    16
#define Hh     192
#define Ww     192
#define Cc     64
#define KKp    9
#define Rr     13
#define TWO_R  26
#define TAU_INV 2.0f
#define NPIX   9
#define N_TILES 7
#define N_TILE_PAIRS 28
#define SIMN   (TWO_R * TWO_R)     // 676

__device__ __align__(16) float g_sim[BSZ][SIMN];  // zero-init, reset each run
__device__ unsigned g_cnt[BSZ];
__device__ float    g_bloss[BSZ];
__device__ unsigned g_done;

__global__ __launch_bounds__(256, 1)
void infonce_split(const float* __restrict__ f1, const float* __restrict__ f2,
                   const int* __restrict__ bi, const int* __restrict__ hi,
                   const int* __restrict__ wi, float* __restrict__ out)
{
    __shared__ float p[28][Cc];            // 26 rows + 2 zero rows
    __shared__ float sim[SIMN];
    __shared__ float rn[32];
    __shared__ float rowloss[8];
    __shared__ int   s_last;

    const int blk  = blockIdx.x;
    const int b    = blk / NPIX;
    const int s    = blk - b * NPIX;       // pixel slice 0..8
    const int tid  = threadIdx.x;
    const int warp = tid >> 5;
    const int lane = tid & 31;

    // ---- Phase 1 (fused): per-thread offset + gather, zero-pad rows 26,27 ----
    // 28 rows x 16 float4 = 448 items; idx loads broadcast across 16 threads.
    #pragma unroll
    for (int it = 0; it < 2; it++) {
        int idx = tid + it * 256;
        if (idx < 28 * 16) {
            int i = idx >> 4, v = idx & 15;
            float4 val = make_float4(0.f, 0.f, 0.f, 0.f);
            if (i < TWO_R) {
                int r = (i < Rr) ? i : (i - Rr);
                int l = (r * BSZ + b) * KKp + s;
                int o = ((bi[l] * Hh + hi[l]) * Ww + wi[l]) * Cc;
                const float* f = (i < Rr) ? f1 : f2;
                val = *(const float4*)(f + o + v * 4);
            }
            ((float4*)p[i])[v] = val;
        }
    }
    __syncthreads();

    // ---- Phase 2: partial Gram (D=64), 4x4 register tiles, warp per pair ----
    for (int t = warp; t < N_TILE_PAIRS; t += 8) {
        int ti = 0, tt = t;
        while (tt >= N_TILES - ti) { tt -= N_TILES - ti; ti++; }
        int tj = ti + tt;

        float acc[4][4];
        #pragma unroll
        for (int a = 0; a < 4; a++)
            #pragma unroll
            for (int c = 0; c < 4; c++) acc[a][c] = 0.f;

        #pragma unroll
        for (int it = 0; it < 2; it++) {
            int d = lane + it * 32;
            float av[4], bv[4];
            #pragma unroll
            for (int a = 0; a < 4; a++) av[a] = p[ti * 4 + a][d];
            #pragma unroll
            for (int c = 0; c < 4; c++) bv[c] = p[tj * 4 + c][d];
            #pragma unroll
            for (int a = 0; a < 4; a++)
                #pragma unroll
                for (int c = 0; c < 4; c++)
                    acc[a][c] = fmaf(av[a], bv[c], acc[a][c]);
        }
        #pragma unroll
        for (int a = 0; a < 4; a++) {
            #pragma unroll
            for (int c = 0; c < 4; c++) {
                float v = acc[a][c];
                #pragma unroll
                for (int o = 16; o > 0; o >>= 1)
                    v += __shfl_down_sync(0xffffffffu, v, o);
                if (lane == 0) {
                    int i = ti * 4 + a, j = tj * 4 + c;
                    if (i < TWO_R && j < TWO_R) {
                        sim[i * TWO_R + j] = v;
                        sim[j * TWO_R + i] = v;
                    }
                }
            }
        }
    }
    __syncthreads();

    // ---- Phase 3: accumulate into global per-batch Gram ----
    for (int e = tid; e < SIMN; e += 256)
        atomicAdd(&g_sim[b][e], sim[e]);
    __syncthreads();
    if (tid == 0) {
        __threadfence();
        s_last = (atomicAdd(&g_cnt[b], 1u) == NPIX - 1);
    }
    __syncthreads();
    if (!s_last) return;

    // ---- Batch-last block: vectorized reload + reset ----
    float4* gs4 = (float4*)g_sim[b];
    if (tid < SIMN / 4)                       // 169 float4, one iter
        ((float4*)sim)[tid] = __ldcg((const float4*)gs4 + tid);
    __syncthreads();
    if (tid < SIMN / 4)
        gs4[tid] = make_float4(0.f, 0.f, 0.f, 0.f);
    if (tid == 0) g_cnt[b] = 0;
    if (tid < TWO_R)
        rn[tid] = 1.f / fmaxf(sqrtf(sim[tid * TWO_R + tid]), 1e-8f);
    __syncthreads();

    // ---- Phase 4: per-row losses, warp per row (lane-parallel over j) ----
    float wl = 0.f;
    for (int i = warp; i < TWO_R; i += 8) {
        bool valid = (lane < TWO_R) && (lane != i);
        float v = valid ? sim[i * TWO_R + lane] * rn[i] * rn[lane] * TAU_INV
                        : -1e30f;
        float m = v;
        #pragma unroll
        for (int o = 16; o > 0; o >>= 1)
            m = fmaxf(m, __shfl_xor_sync(0xffffffffu, m, o));
        float e = valid ? __expf(v - m) : 0.f;
        #pragma unroll
        for (int o = 16; o > 0; o >>= 1)
            e += __shfl_xor_sync(0xffffffffu, e, o);
        int partner = (i + Rr) % TWO_R;
        float pv = __shfl_sync(0xffffffffu, v, partner);
        if (lane == 0) wl += __logf(e) + m - pv;
    }
    if (lane == 0) rowloss[warp] = wl;
    __syncthreads();

    // ---- Phase 5: batch loss store; 16th finisher sums + writes out ----
    if (tid == 0) {
        float total = 0.f;
        #pragma unroll
        for (int k = 0; k < 8; k++) total += rowloss[k];
        g_bloss[b] = total;                    // plain store, fenced below
        __threadfence();
        if (atomicAdd(&g_done, 1u) == BSZ - 1) {
            float tl = 0.f;
            #pragma unroll
            for (int k = 0; k < BSZ; k++) tl += __ldcg(&g_bloss[k]);
            out[0] = tl / (float)(BSZ * TWO_R);
            g_done = 0;
        }
    }
}

extern "C" void kernel_launch(void* const* d_in, const int* in_sizes, int n_in,
                              void* d_out, int out_size)
{
    const float* f1 = (const float*)d_in[0];
    const float* f2 = (const float*)d_in[1];
    const int*   bi = (const int*)d_in[2];
    const int*   hi = (const int*)d_in[3];
    const int*   wi = (const int*)d_in[4];
    float* out = (float*)d_out;

    infonce_split<<<BSZ * NPIX, 256>>>(f1, f2, bi, hi, wi, out);
}